// round 8
// baseline (speedup 1.0000x reference)
#include <cuda_runtime.h>
#include <cuda_bf16.h>
#include <math.h>
#include <stdint.h>

// ---------------- problem constants ----------------
#define BSZ     2
#define SEQL    4096
#define DMODEL  768
#define DSTATE  128
#define HD      64
#define DIN     1536
#define NH      24
#define DXBC    1792          // DIN + 2*DSTATE
#define DPROJ   3352          // 2*DIN + 2*DSTATE + NH
#define CHUNKQ  128
#define NCH     32            // SEQL / CHUNKQ
#define NROWS   (BSZ*SEQL)    // 8192
#define NBC     (BSZ*NCH)     // 64

// single shared-memory extern symbol (consistent across all kernels)
extern __shared__ __align__(128) char smbuf[];

// ---------------- scratch (static device memory; no runtime allocs) ----------------
__device__ float g_zx[(size_t)NROWS*DPROJ];
__device__ float g_xbc[(size_t)NROWS*DXBC];
__device__ float g_dt[NROWS*NH];
__device__ float g_acum[NROWS*NH];
__device__ float g_alast[NBC*NH];
__device__ float g_cb[(size_t)NBC*CHUNKQ*CHUNKQ];
__device__ float g_states[(size_t)NBC*NH*HD*DSTATE];
__device__ float g_prev[(size_t)NBC*NH*HD*DSTATE];
__device__ float g_y[(size_t)NROWS*DIN];

// ================= helpers (family-target safe) =================
__device__ __forceinline__ uint32_t smem_u32(const void* p) {
    uint32_t a;
    asm("{ .reg .u64 t; cvta.to.shared.u64 t, %1; cvt.u32.u64 %0, t; }" : "=r"(a) : "l"(p));
    return a;
}
__device__ __forceinline__ void ldsm4(uint32_t* r, uint32_t addr) {
    asm volatile("ldmatrix.sync.aligned.m8n8.x4.shared.b16 {%0,%1,%2,%3}, [%4];"
                 : "=r"(r[0]), "=r"(r[1]), "=r"(r[2]), "=r"(r[3]) : "r"(addr));
}
__device__ __forceinline__ void mma16816(float* d, const uint32_t* a, const uint32_t* b,
                                         const float* c) {
    asm volatile("mma.sync.aligned.m16n8k16.row.col.f32.bf16.bf16.f32 "
        "{%0,%1,%2,%3}, {%4,%5,%6,%7}, {%8,%9}, {%10,%11,%12,%13};"
        : "=f"(d[0]), "=f"(d[1]), "=f"(d[2]), "=f"(d[3])
        : "r"(a[0]), "r"(a[1]), "r"(a[2]), "r"(a[3]), "r"(b[0]), "r"(b[1]),
          "f"(c[0]), "f"(c[1]), "f"(c[2]), "f"(c[3]));
}
__device__ __forceinline__ void sts64(uint32_t addr, uint32_t x, uint32_t y) {
    asm volatile("st.shared.v2.b32 [%0], {%1,%2};" :: "r"(addr), "r"(x), "r"(y));
}
#define SWZ128(x) ((x) ^ (((x) >> 3) & 0x70))
#define SWZ256(x) ((x) ^ (((x) >> 4) & 0x70))

// convert float4 -> packed hi (2x u32) and lo (2x u32) bf16 pairs
__device__ __forceinline__ void cvt_split4(float4 f, uint32_t& h01, uint32_t& h23,
                                           uint32_t& l01, uint32_t& l23) {
    float v[4] = {f.x, f.y, f.z, f.w};
    uint32_t h[4], l[4];
    #pragma unroll
    for (int i = 0; i < 4; ++i) {
        __nv_bfloat16 hb = __float2bfloat16(v[i]);
        __nv_bfloat16 lb = __float2bfloat16(v[i] - __bfloat162float(hb));
        h[i] = (uint32_t)__bfloat16_as_ushort(hb);
        l[i] = (uint32_t)__bfloat16_as_ushort(lb);
    }
    h01 = h[0] | (h[1] << 16); h23 = h[2] | (h[3] << 16);
    l01 = l[0] | (l[1] << 16); l23 = l[2] | (l[3] << 16);
}

__device__ __forceinline__ void split_store(char* hi_base, char* lo_base, uint32_t off, float v) {
    __nv_bfloat16 hi = __float2bfloat16(v);
    __nv_bfloat16 lo = __float2bfloat16(v - __bfloat162float(hi));
    *(__nv_bfloat16*)(hi_base + off) = hi;
    *(__nv_bfloat16*)(lo_base + off) = lo;
}

// ================= fused fp32 -> split-bf16 GEMM: C[M,Nreal] = A[M,K] * B[Nreal,K]^T =================
// 128x128 CTA tile, K-chunk 64, double-buffered smem (2 x 64KB), 3 mma passes per chunk:
// Ahi*Bhi + Ahi*Blo + Alo*Bhi (lo*lo dropped, ~2^-16 relative).
// stage layout: Ahi@0, Alo@16K, Bhi@32K, Blo@48K (bf16, 128B rows, SWZ128)
#define GEMM_SMEM_BYTES (1024 + 2*65536)
__global__ __launch_bounds__(256, 1)
void gemm_fused(const float* __restrict__ A, const float* __restrict__ B,
                float* __restrict__ C, int K, int Nreal, int ldc,
                const float* __restrict__ feat, const float* __restrict__ gate1, int ep)
{
    const uint32_t base = (smem_u32(smbuf) + 1023) & ~1023u;
    const int tid  = threadIdx.x;
    const int lane = tid & 31;
    const int wid  = tid >> 5;
    const int m0 = blockIdx.y * 128;
    const int n0 = blockIdx.x * 128;
    const int wm = wid >> 2;
    const int wn = wid & 3;

    // fill mapping: 16 threads per row (fully coalesced 256B fp32 rows), 8 row-groups
    const int frow = tid >> 4;       // 0..15 (+ j*16)
    const int fu   = tid & 15;       // float4 slot in row
    const float* agp = A + (size_t)(m0 + frow) * K + fu * 4;
    const float* bgp = B + (size_t)(n0 + frow) * K + fu * 4;

    uint32_t soff[8];
    bool bok[8];
    #pragma unroll
    for (int j = 0; j < 8; ++j) {
        soff[j] = SWZ128((frow + j*16)*128 + fu*8);
        bok[j]  = (n0 + frow + j*16) < Nreal;
    }

    float acc[4][4][4] = {};
    const int nch = K >> 6;
    float4 ar[8], br[8];

    // prologue: load + convert + store chunk 0
    #pragma unroll
    for (int j = 0; j < 8; ++j) {
        ar[j] = *(const float4*)(agp + (size_t)(j*16)*K);
        br[j] = bok[j] ? *(const float4*)(bgp + (size_t)(j*16)*K)
                       : make_float4(0.f, 0.f, 0.f, 0.f);
    }
    #pragma unroll
    for (int j = 0; j < 8; ++j) {
        uint32_t h01, h23, l01, l23;
        cvt_split4(ar[j], h01, h23, l01, l23);
        sts64(base + soff[j],         h01, h23);
        sts64(base + 16384 + soff[j], l01, l23);
        cvt_split4(br[j], h01, h23, l01, l23);
        sts64(base + 32768 + soff[j], h01, h23);
        sts64(base + 49152 + soff[j], l01, l23);
    }
    __syncthreads();

    for (int c = 0; c < nch; ++c) {
        // issue gmem loads for next chunk (hidden under this chunk's mma)
        if (c + 1 < nch) {
            const float* a = agp + (c+1)*64;
            const float* b = bgp + (c+1)*64;
            #pragma unroll
            for (int j = 0; j < 8; ++j) {
                ar[j] = *(const float4*)(a + (size_t)(j*16)*K);
                br[j] = bok[j] ? *(const float4*)(b + (size_t)(j*16)*K)
                               : make_float4(0.f, 0.f, 0.f, 0.f);
            }
        }
        // 3-pass mma over resident tiles
        const uint32_t st = base + (c & 1) * 65536;
        const uint32_t AO[3] = {0u, 0u, 16384u};
        const uint32_t BO[3] = {32768u, 49152u, 32768u};
        #pragma unroll
        for (int pp = 0; pp < 3; ++pp) {
            const uint32_t ab = st + AO[pp], bb = st + BO[pp];
            #pragma unroll
            for (int ks = 0; ks < 4; ++ks) {
                uint32_t a_r[4][4], b_r[2][4];
                const int ra = wm*64 + ((lane>>3)&1)*8 + (lane&7);
                const int ka = ks*32 + ((lane>>4)&1)*16;
                #pragma unroll
                for (int mf = 0; mf < 4; ++mf)
                    ldsm4(a_r[mf], ab + SWZ128((ra + mf*16)*128 + ka));
                const int rb = wn*32 + ((lane>>4)&1)*8 + (lane&7);
                const int kb = ks*32 + ((lane>>3)&1)*16;
                #pragma unroll
                for (int nf2 = 0; nf2 < 2; ++nf2)
                    ldsm4(b_r[nf2], bb + SWZ128((rb + nf2*16)*128 + kb));
                #pragma unroll
                for (int mf = 0; mf < 4; ++mf)
                    #pragma unroll
                    for (int nf = 0; nf < 4; ++nf)
                        mma16816(acc[mf][nf], a_r[mf], &b_r[nf>>1][(nf&1)*2], acc[mf][nf]);
            }
        }
        __syncthreads();
        if (c + 1 < nch) {
            const uint32_t nst = base + ((c+1) & 1) * 65536;
            #pragma unroll
            for (int j = 0; j < 8; ++j) {
                uint32_t h01, h23, l01, l23;
                cvt_split4(ar[j], h01, h23, l01, l23);
                sts64(nst + soff[j],         h01, h23);
                sts64(nst + 16384 + soff[j], l01, l23);
                cvt_split4(br[j], h01, h23, l01, l23);
                sts64(nst + 32768 + soff[j], h01, h23);
                sts64(nst + 49152 + soff[j], l01, l23);
            }
            __syncthreads();
        }
    }

    // epilogue
    float g = 0.f;
    if (ep) g = 1.f / (1.f + expf(-gate1[0]));
    const int mrow = m0 + wm*64 + (lane >> 2);
    const int nbase = n0 + wn*32 + (lane & 3)*2;
    #pragma unroll
    for (int mf = 0; mf < 4; ++mf) {
        #pragma unroll
        for (int nf = 0; nf < 4; ++nf) {
            int m = mrow + mf*16;
            int n = nbase + nf*8;
            if (n < Nreal) {
                float2 v0 = make_float2(acc[mf][nf][0], acc[mf][nf][1]);
                float2 v1 = make_float2(acc[mf][nf][2], acc[mf][nf][3]);
                if (ep) {
                    float2 f0 = *(const float2*)(feat + (size_t)m*ldc + n);
                    float2 f1 = *(const float2*)(feat + (size_t)(m+8)*ldc + n);
                    v0.x = g*v0.x + f0.x; v0.y = g*v0.y + f0.y;
                    v1.x = g*v1.x + f1.x; v1.y = g*v1.y + f1.y;
                }
                *(float2*)(C + (size_t)m*ldc + n)     = v0;
                *(float2*)(C + (size_t)(m+8)*ldc + n) = v1;
            }
        }
    }
}

// ---------------- depthwise causal conv (width 4) + bias + SiLU, 4 rows/thread ----------------
__global__ void conv_silu_kernel(const float* __restrict__ cw, const float* __restrict__ cb)
{
    int ch = blockIdx.x * 256 + threadIdx.x;        // 0..DXBC-1 (DXBC = 7*256)
    int r0 = blockIdx.y * 4;
    int l0 = r0 % SEQL;
    float w0 = cw[ch*4+0], w1 = cw[ch*4+1], w2 = cw[ch*4+2], w3 = cw[ch*4+3];
    float bias = cb[ch];
    float v[7];
    #pragma unroll
    for (int t = 0; t < 7; ++t) {
        int lr = l0 + t - 3;
        v[t] = (lr >= 0) ? g_zx[(size_t)(r0 + t - 3) * DPROJ + DIN + ch] : 0.f;
    }
    #pragma unroll
    for (int j = 0; j < 4; ++j) {
        float acc = bias + w0*v[j] + w1*v[j+1] + w2*v[j+2] + w3*v[j+3];
        g_xbc[(size_t)(r0 + j) * DXBC + ch] = acc / (1.f + __expf(-acc));
    }
}

// ---------------- dt = softplus(raw + dt_bias) ----------------
__global__ void dt_kernel(const float* __restrict__ dt_bias)
{
    int idx = blockIdx.x * blockDim.x + threadIdx.x;
    if (idx >= NROWS * NH) return;
    int h   = idx % NH;
    int row = idx / NH;
    float v = g_zx[(size_t)row * DPROJ + (DIN + DXBC) + h] + dt_bias[h];
    g_dt[idx] = (v > 20.f) ? v : log1pf(expf(v));
}

// ---------------- per-chunk inclusive cumsum of dt*A ----------------
__global__ void acum_kernel(const float* __restrict__ A_log)
{
    int h  = blockIdx.x % NH;
    int bc = blockIdx.x / NH;
    int l  = threadIdx.x;
    __shared__ float s[CHUNKQ];
    float Ah = -expf(A_log[h]);
    int row = bc * CHUNKQ + l;
    s[l] = g_dt[row * NH + h] * Ah;
    __syncthreads();
    for (int off = 1; off < CHUNKQ; off <<= 1) {
        float v = (l >= off) ? s[l - off] : 0.f;
        __syncthreads();
        s[l] += v;
        __syncthreads();
    }
    g_acum[row * NH + h] = s[l];
    if (l == CHUNKQ - 1) g_alast[bc * NH + h] = s[l];
}

// ---------------- CB[l,s] = sum_n C[l,n]*B[s,n] per chunk (fp32, feeds W) ----------------
#define CB_SMEM_BYTES ((CHUNKQ*CHUNKQ + CHUNKQ*132) * 4)
__global__ void cb_kernel()
{
    float* sm  = (float*)smbuf;
    float* Cs  = sm;
    float* BsT = sm + CHUNKQ*CHUNKQ;
    int bc  = blockIdx.x;
    int tid = threadIdx.x;
    int row0 = bc * CHUNKQ;
    for (int i = tid; i < CHUNKQ*CHUNKQ; i += 256) {
        int l = i >> 7, n = i & 127;
        const float* base = &g_xbc[(size_t)(row0 + l) * DXBC];
        Cs[i]            = base[DIN + DSTATE + n];
        BsT[n*132 + l]   = base[DIN + n];
    }
    __syncthreads();
    int l  = tid >> 1;
    int s0 = (tid & 1) * 64;
    float acc[64] = {};
    for (int n = 0; n < 128; n++) {
        float cv = Cs[l*128 + n];
        const float4* bp = (const float4*)&BsT[n*132 + s0];
        #pragma unroll
        for (int j4 = 0; j4 < 16; j4++) {
            float4 b = bp[j4];
            acc[4*j4+0] += cv*b.x; acc[4*j4+1] += cv*b.y;
            acc[4*j4+2] += cv*b.z; acc[4*j4+3] += cv*b.w;
        }
    }
    float* outp = &g_cb[(size_t)bc*CHUNKQ*CHUNKQ + l*CHUNKQ + s0];
    #pragma unroll
    for (int j4 = 0; j4 < 16; j4++)
        ((float4*)outp)[j4] = make_float4(acc[4*j4], acc[4*j4+1], acc[4*j4+2], acc[4*j4+3]);
}

// ================= states via mma.sync (split bf16) =================
#define STM_SMEM_BYTES 98304
__global__ __launch_bounds__(128, 2) void states_mma()
{
    char* sm = smbuf;
    __shared__ float wfac[128];
    const int h  = blockIdx.x % NH;
    const int bc = blockIdx.x / NH;
    const int tid = threadIdx.x;
    const int row0 = bc * CHUNKQ;

    if (tid < 128) {
        float alast = g_alast[bc*NH + h];
        wfac[tid] = g_dt[(row0+tid)*NH + h] * __expf(alast - g_acum[(row0+tid)*NH + h]);
    }
    __syncthreads();
    for (int i = tid; i < 8192; i += 128) {
        int l = i >> 6, p = i & 63;
        float v = g_xbc[(size_t)(row0+l)*DXBC + h*HD + p] * wfac[l];
        split_store(sm, sm + 16384, SWZ256(p*256 + l*2), v);
    }
    for (int i = tid; i < 16384; i += 128) {
        int l = i >> 7, n = i & 127;
        float v = g_xbc[(size_t)(row0+l)*DXBC + DIN + n];
        split_store(sm + 32768, sm + 65536, SWZ256(n*256 + l*2), v);
    }
    __syncthreads();

    const int lane = tid & 31;
    const int w = tid >> 5;
    const uint32_t base = smem_u32(sm);
    float acc[4][4][4] = {};
    const uint32_t AO[3] = {0u, 0u, 16384u};
    const uint32_t BO[3] = {32768u, 65536u, 32768u};
    #pragma unroll
    for (int pp = 0; pp < 3; ++pp) {
        const uint32_t ab = base + AO[pp], bb = base + BO[pp];
        #pragma unroll
        for (int ks = 0; ks < 8; ++ks) {
            uint32_t a_r[4][4], b_r[2][4];
            const int ra = ((lane>>3)&1)*8 + (lane&7);
            const int ca = ks*32 + ((lane>>4)&1)*16;
            #pragma unroll
            for (int mf = 0; mf < 4; ++mf)
                ldsm4(a_r[mf], ab + SWZ256((ra + mf*16)*256 + ca));
            const int rb = w*32 + ((lane>>4)&1)*8 + (lane&7);
            const int cb2 = ks*32 + ((lane>>3)&1)*16;
            #pragma unroll
            for (int nf2 = 0; nf2 < 2; ++nf2)
                ldsm4(b_r[nf2], bb + SWZ256((rb + nf2*16)*256 + cb2));
            #pragma unroll
            for (int mf = 0; mf < 4; ++mf)
                #pragma unroll
                for (int nf = 0; nf < 4; ++nf)
                    mma16816(acc[mf][nf], a_r[mf], &b_r[nf>>1][(nf&1)*2], acc[mf][nf]);
        }
    }
    float* outb = &g_states[((size_t)(bc*NH) + h) * HD * DSTATE];
    const int mr = lane >> 2;
    const int nb = w*32 + (lane & 3)*2;
    #pragma unroll
    for (int mf = 0; mf < 4; ++mf) {
        #pragma unroll
        for (int nf = 0; nf < 4; ++nf) {
            int p = mf*16 + mr, n = nb + nf*8;
            *(float2*)&outb[p*DSTATE + n]       = make_float2(acc[mf][nf][0], acc[mf][nf][1]);
            *(float2*)&outb[(p+8)*DSTATE + n]   = make_float2(acc[mf][nf][2], acc[mf][nf][3]);
        }
    }
}

// ---------------- inter-chunk state recurrence (one lane per thread) ----------------
__global__ void scan_kernel()
{
    int gl = blockIdx.x * blockDim.x + threadIdx.x;
    int bh = gl >> 13;
    int b = bh / NH, h = bh % NH;
    int e = gl & 8191;
    float S = 0.f;
    for (int c = 0; c < NCH; c++) {
        int bc = b*NCH + c;
        size_t base = ((size_t)(bc*NH) + h) * HD * DSTATE;
        float ed = __expf(g_alast[bc*NH + h]);
        float st = g_states[base + e];
        g_prev[base + e] = S;
        S = S*ed + st;
    }
}

// ================= Y via mma.sync (split bf16) =================
#define YM_SMEM_BYTES 98304
__device__ __forceinline__ void y_mma_block(float acc[2][4][4], uint32_t base,
                                            int lane, int wm, int wn)
{
    const uint32_t AO[3] = {0u, 0u, 32768u};
    const uint32_t BO[3] = {65536u, 81920u, 65536u};
    #pragma unroll
    for (int pp = 0; pp < 3; ++pp) {
        const uint32_t ab = base + AO[pp], bb = base + BO[pp];
        #pragma unroll
        for (int ks = 0; ks < 8; ++ks) {
            uint32_t a_r[2][4], b_r[2][4];
            const int ra = wm*32 + ((lane>>3)&1)*8 + (lane&7);
            const int ca = ks*32 + ((lane>>4)&1)*16;
            #pragma unroll
            for (int mf = 0; mf < 2; ++mf)
                ldsm4(a_r[mf], ab + SWZ256((ra + mf*16)*256 + ca));
            const int rb = wn*32 + ((lane>>4)&1)*8 + (lane&7);
            const int cb2 = ks*32 + ((lane>>3)&1)*16;
            #pragma unroll
            for (int nf2 = 0; nf2 < 2; ++nf2)
                ldsm4(b_r[nf2], bb + SWZ256((rb + nf2*16)*256 + cb2));
            #pragma unroll
            for (int mf = 0; mf < 2; ++mf)
                #pragma unroll
                for (int nf = 0; nf < 4; ++nf)
                    mma16816(acc[mf][nf], a_r[mf], &b_r[nf>>1][(nf&1)*2], acc[mf][nf]);
        }
    }
}

__global__ __launch_bounds__(256, 2) void y_mma(const float* __restrict__ Dv)
{
    char* sm = smbuf;
    __shared__ float acum_s[128], dt_s[128], eAl_s[128];
    const int h  = blockIdx.x % NH;
    const int bc = blockIdx.x / NH;
    const int tid = threadIdx.x;
    const int row0 = bc * CHUNKQ;

    if (tid < 128) {
        float a = g_acum[(row0+tid)*NH + h];
        acum_s[tid] = a;
        eAl_s[tid]  = __expf(a);
        dt_s[tid]   = g_dt[(row0+tid)*NH + h];
    }
    __syncthreads();

    for (int i = tid; i < 16384; i += 256) {
        int l = i >> 7, n = i & 127;
        float v = g_xbc[(size_t)(row0+l)*DXBC + DIN + DSTATE + n] * eAl_s[l];
        split_store(sm, sm + 32768, SWZ256(l*256 + n*2), v);
    }
    const size_t pbase = ((size_t)(bc*NH) + h) * HD * DSTATE;
    for (int i = tid; i < 8192; i += 256) {
        int p = i >> 7, n = i & 127;
        float v = g_prev[pbase + i];
        split_store(sm + 65536, sm + 81920, SWZ256(p*256 + n*2), v);
    }
    __syncthreads();

    const int lane = tid & 31;
    const int wid = tid >> 5;
    const int wm = wid >> 1;
    const int wn = wid & 1;
    const uint32_t base = smem_u32(sm);
    float acc[2][4][4] = {};
    y_mma_block(acc, base, lane, wm, wn);
    __syncthreads();

    for (int i = tid; i < 16384; i += 256) {
        int l = i >> 7, s = i & 127;
        float v = 0.f;
        if (s <= l)
            v = g_cb[(size_t)bc*CHUNKQ*CHUNKQ + i] * __expf(acum_s[l] - acum_s[s]) * dt_s[s];
        split_store(sm, sm + 32768, SWZ256(l*256 + s*2), v);
    }
    for (int i = tid; i < 8192; i += 256) {
        int l = i >> 6, p = i & 63;
        float v = g_xbc[(size_t)(row0+l)*DXBC + h*HD + p];
        split_store(sm + 65536, sm + 81920, SWZ256(p*256 + l*2), v);
    }
    __syncthreads();
    y_mma_block(acc, base, lane, wm, wn);

    const float dval = Dv[h];
    const int mr = lane >> 2;
    const int nb = (lane & 3)*2;
    #pragma unroll
    for (int mf = 0; mf < 2; ++mf) {
        #pragma unroll
        for (int nf = 0; nf < 4; ++nf) {
            int p = wn*32 + nf*8 + nb;
            #pragma unroll
            for (int rr = 0; rr < 2; ++rr) {
                int l = wm*32 + mf*16 + mr + rr*8;
                uint32_t o0 = SWZ256(p*256 + l*2);
                uint32_t o1 = SWZ256((p+1)*256 + l*2);
                float x0 = __bfloat162float(*(__nv_bfloat16*)(sm + 65536 + o0))
                         + __bfloat162float(*(__nv_bfloat16*)(sm + 81920 + o0));
                float x1 = __bfloat162float(*(__nv_bfloat16*)(sm + 65536 + o1))
                         + __bfloat162float(*(__nv_bfloat16*)(sm + 81920 + o1));
                float2 v = make_float2(acc[mf][nf][rr*2+0] + dval*x0,
                                       acc[mf][nf][rr*2+1] + dval*x1);
                *(float2*)&g_y[(size_t)(row0+l)*DIN + h*HD + p] = v;
            }
        }
    }
}

// ---------------- gating + RMSNorm ----------------
__global__ void norm_kernel(const float* __restrict__ norm_w)
{
    __shared__ float tbuf[DIN];
    __shared__ float red[256];
    int row = blockIdx.x;
    int tid = threadIdx.x;
    float partial = 0.f;
    for (int i = tid; i < DIN; i += 256) {
        float yv = g_y[(size_t)row*DIN + i];
        float zv = g_zx[(size_t)row*DPROJ + i];
        float t  = yv * (zv / (1.f + __expf(-zv)));
        tbuf[i] = t;
        partial += t*t;
    }
    red[tid] = partial;
    __syncthreads();
    for (int s = 128; s > 0; s >>= 1) {
        if (tid < s) red[tid] += red[tid + s];
        __syncthreads();
    }
    float scale = rsqrtf(red[0] / (float)DIN + 1e-5f);
    for (int i = tid; i < DIN; i += 256)
        g_y[(size_t)row*DIN + i] = tbuf[i] * scale * norm_w[i];
}

// ---------------- launch ----------------
extern "C" void kernel_launch(void* const* d_in, const int* in_sizes, int n_in,
                              void* d_out, int out_size)
{
    const float* feature = (const float*)d_in[0];
    const float* gate1   = (const float*)d_in[1];
    const float* in_w    = (const float*)d_in[2];
    const float* conv_w  = (const float*)d_in[3];
    const float* conv_b  = (const float*)d_in[4];
    const float* dt_bias = (const float*)d_in[5];
    const float* A_log   = (const float*)d_in[6];
    const float* Dv      = (const float*)d_in[7];
    const float* norm_w  = (const float*)d_in[8];
    const float* out_w   = (const float*)d_in[9];
    float* out = (float*)d_out;

    void* p_zx; cudaGetSymbolAddress(&p_zx, g_zx);
    void* p_y;  cudaGetSymbolAddress(&p_y,  g_y);

    cudaFuncSetAttribute(cb_kernel,  cudaFuncAttributeMaxDynamicSharedMemorySize, CB_SMEM_BYTES);
    cudaFuncSetAttribute(states_mma, cudaFuncAttributeMaxDynamicSharedMemorySize, STM_SMEM_BYTES);
    cudaFuncSetAttribute(y_mma,      cudaFuncAttributeMaxDynamicSharedMemorySize, YM_SMEM_BYTES);
    cudaFuncSetAttribute(gemm_fused, cudaFuncAttributeMaxDynamicSharedMemorySize, GEMM_SMEM_BYTES);

    // 1. zxbcdt = feature @ in_proj_w^T  (fused split + tensor cores)
    gemm_fused<<<dim3(27, NROWS/128), 256, GEMM_SMEM_BYTES>>>(
        feature, in_w, (float*)p_zx, DMODEL, DPROJ, DPROJ, nullptr, nullptr, 0);
    // 2. conv + silu (4 rows per thread)
    conv_silu_kernel<<<dim3(DXBC/256, NROWS/4), 256>>>(conv_w, conv_b);
    // 3. dt, per-chunk cumsum
    dt_kernel<<<(NROWS*NH + 255)/256, 256>>>(dt_bias);
    acum_kernel<<<NBC*NH, CHUNKQ>>>(A_log);
    // 4. CB per chunk (fp32)
    cb_kernel<<<NBC, 256, CB_SMEM_BYTES>>>();
    // 5. chunk states (tensor cores, split bf16)
    states_mma<<<NBC*NH, 128, STM_SMEM_BYTES>>>();
    // 6. inter-chunk recurrence
    scan_kernel<<<(BSZ*NH*HD*DSTATE)/512, 512>>>();
    // 7. Y (tensor cores, split bf16)
    y_mma<<<NBC*NH, 256, YM_SMEM_BYTES>>>(Dv);
    // 8. gating + RMSNorm
    norm_kernel<<<NROWS, 256>>>(norm_w);
    // 9. out = sigmoid(gate1) * (y @ out_proj_w^T) + feature  (fused split + tensor cores)
    gemm_fused<<<dim3(6, NROWS/128), 256, GEMM_SMEM_BYTES>>>(
        (const float*)p_y, out_w, out, DIN, DMODEL, DMODEL, feature, gate1, 1);
}

// round 9
// speedup vs baseline: 1.3536x; 1.3536x over previous
#include <cuda_runtime.h>
#include <cuda_bf16.h>
#include <math.h>
#include <stdint.h>

// ---------------- problem constants ----------------
#define BSZ     2
#define SEQL    4096
#define DMODEL  768
#define DSTATE  128
#define HD      64
#define DIN     1536
#define NH      24
#define DXBC    1792          // DIN + 2*DSTATE
#define DPROJ   3352          // 2*DIN + 2*DSTATE + NH
#define CHUNKQ  128
#define NCH     32            // SEQL / CHUNKQ
#define NROWS   (BSZ*SEQL)    // 8192
#define NBC     (BSZ*NCH)     // 64

#define KP1     (3*DMODEL)    // 2304
#define KP2     (3*DIN)       // 4608
#define NPAD1   3456          // 27*128

// single shared-memory extern symbol (consistent across all kernels)
extern __shared__ __align__(128) char smbuf[];

// ---------------- scratch (static device memory; no runtime allocs) ----------------
__device__ float g_zx[(size_t)NROWS*DPROJ];
__device__ float g_xbc[(size_t)NROWS*DXBC];
__device__ float g_dt[NROWS*NH];
__device__ float g_acum[NROWS*NH];
__device__ float g_alast[NBC*NH];
__device__ float g_cb[(size_t)NBC*CHUNKQ*CHUNKQ];
__device__ float g_states[(size_t)NBC*NH*HD*DSTATE];
__device__ float g_prev[(size_t)NBC*NH*HD*DSTATE];
__device__ float g_y[(size_t)NROWS*DIN];
__device__ __nv_bfloat16 g_a2[(size_t)NROWS*KP2];
__device__ __nv_bfloat16 g_b2[(size_t)NPAD1*KP1];

// ================= helpers (family-target safe) =================
__device__ __forceinline__ uint32_t smem_u32(const void* p) {
    uint32_t a;
    asm("{ .reg .u64 t; cvta.to.shared.u64 t, %1; cvt.u32.u64 %0, t; }" : "=r"(a) : "l"(p));
    return a;
}
__device__ __forceinline__ void cpasync16(uint32_t dst, const void* src) {
    asm volatile("cp.async.cg.shared.global [%0], [%1], 16;" :: "r"(dst), "l"(src) : "memory");
}
__device__ __forceinline__ void ldsm4(uint32_t* r, uint32_t addr) {
    asm volatile("ldmatrix.sync.aligned.m8n8.x4.shared.b16 {%0,%1,%2,%3}, [%4];"
                 : "=r"(r[0]), "=r"(r[1]), "=r"(r[2]), "=r"(r[3]) : "r"(addr));
}
__device__ __forceinline__ void mma16816(float* d, const uint32_t* a, const uint32_t* b,
                                         const float* c) {
    asm volatile("mma.sync.aligned.m16n8k16.row.col.f32.bf16.bf16.f32 "
        "{%0,%1,%2,%3}, {%4,%5,%6,%7}, {%8,%9}, {%10,%11,%12,%13};"
        : "=f"(d[0]), "=f"(d[1]), "=f"(d[2]), "=f"(d[3])
        : "r"(a[0]), "r"(a[1]), "r"(a[2]), "r"(a[3]), "r"(b[0]), "r"(b[1]),
          "f"(c[0]), "f"(c[1]), "f"(c[2]), "f"(c[3]));
}
#define SWZ128(x) ((x) ^ (((x) >> 3) & 0x70))
#define SWZ256(x) ((x) ^ (((x) >> 4) & 0x70))

__device__ __forceinline__ void split_store(char* hi_base, char* lo_base, uint32_t off, float v) {
    __nv_bfloat16 hi = __float2bfloat16(v);
    __nv_bfloat16 lo = __float2bfloat16(v - __bfloat162float(hi));
    *(__nv_bfloat16*)(hi_base + off) = hi;
    *(__nv_bfloat16*)(lo_base + off) = lo;
}

// ================= split-precision conversion for GEMM1 =================
__global__ void split_a_kernel(const float* __restrict__ X, __nv_bfloat16* __restrict__ O,
                               int M, int K)
{
    int idx = blockIdx.x * blockDim.x + threadIdx.x;
    if (idx >= M * K) return;
    int m = idx / K, k = idx % K;
    float x = X[idx];
    __nv_bfloat16 hi = __float2bfloat16(x);
    __nv_bfloat16 lo = __float2bfloat16(x - __bfloat162float(hi));
    size_t base = (size_t)m * 3 * K;
    O[base + k] = hi; O[base + K + k] = hi; O[base + 2*K + k] = lo;
}
__global__ void split_b_kernel(const float* __restrict__ W, __nv_bfloat16* __restrict__ O,
                               int Nreal, int Npad, int K)
{
    int idx = blockIdx.x * blockDim.x + threadIdx.x;
    if (idx >= Npad * K) return;
    int n = idx / K, k = idx % K;
    __nv_bfloat16 hi = __float2bfloat16(0.f), lo = hi;
    if (n < Nreal) {
        float x = W[(size_t)n * K + k];
        hi = __float2bfloat16(x);
        lo = __float2bfloat16(x - __bfloat162float(hi));
    }
    size_t base = (size_t)n * 3 * K;
    O[base + k] = hi; O[base + K + k] = lo; O[base + 2*K + k] = hi;
}

// ================= mma.sync bf16 GEMM (verified R5/R7 shape) =================
#define GEMM_SMEM_BYTES (1024 + 2*32768)
__global__ __launch_bounds__(256, 2)
void gemm_mma(const __nv_bfloat16* __restrict__ A2, const __nv_bfloat16* __restrict__ B2,
              float* __restrict__ C, int KP, int Nreal, int ldc,
              const float* __restrict__ feat, const float* __restrict__ gate1, int ep)
{
    const uint32_t base = (smem_u32(smbuf) + 1023) & ~1023u;
    const int tid  = threadIdx.x;
    const int lane = tid & 31;
    const int wid  = tid >> 5;
    const int m0 = blockIdx.y * 128;
    const int n0 = blockIdx.x * 128;
    const int wm = wid >> 2;
    const int wn = wid & 3;

    const int frow = tid >> 3;
    const int u16  = tid & 7;
    const __nv_bfloat16* ag = A2 + (size_t)(m0 + frow) * KP + u16 * 8;
    const __nv_bfloat16* bg = B2 + (size_t)(n0 + frow) * KP + u16 * 8;

    float acc[4][4][4] = {};
    const int nch = KP >> 6;

    uint32_t foff[4];
    #pragma unroll
    for (int j = 0; j < 4; ++j)
        foff[j] = SWZ128((frow + j*32)*128 + u16*16);

    {
        uint32_t ab = base, bb = base + 16384;
        #pragma unroll
        for (int j = 0; j < 4; ++j) {
            cpasync16(ab + foff[j], ag + (size_t)(j*32)*KP);
            cpasync16(bb + foff[j], bg + (size_t)(j*32)*KP);
        }
        asm volatile("cp.async.commit_group;" ::: "memory");
    }

    for (int c = 0; c < nch; ++c) {
        if (c + 1 < nch) {
            uint32_t ab = base + ((c+1)&1) * 32768, bb = ab + 16384;
            const __nv_bfloat16* a = ag + (c+1) * 64;
            const __nv_bfloat16* b = bg + (c+1) * 64;
            #pragma unroll
            for (int j = 0; j < 4; ++j) {
                cpasync16(ab + foff[j], a + (size_t)(j*32)*KP);
                cpasync16(bb + foff[j], b + (size_t)(j*32)*KP);
            }
            asm volatile("cp.async.commit_group;" ::: "memory");
            asm volatile("cp.async.wait_group 1;" ::: "memory");
        } else {
            asm volatile("cp.async.wait_group 0;" ::: "memory");
        }
        __syncthreads();

        const uint32_t ab = base + (c&1) * 32768;
        const uint32_t bb = ab + 16384;
        #pragma unroll
        for (int ks = 0; ks < 4; ++ks) {
            uint32_t a_r[4][4];
            uint32_t b_r[2][4];
            {
                const int ra = wm*64 + ((lane>>3)&1)*8 + (lane&7);
                const int ka = ks*32 + ((lane>>4)&1)*16;
                #pragma unroll
                for (int mf = 0; mf < 4; ++mf)
                    ldsm4(a_r[mf], ab + SWZ128((ra + mf*16)*128 + ka));
            }
            {
                const int rb = wn*32 + ((lane>>4)&1)*8 + (lane&7);
                const int kb = ks*32 + ((lane>>3)&1)*16;
                #pragma unroll
                for (int nf2 = 0; nf2 < 2; ++nf2)
                    ldsm4(b_r[nf2], bb + SWZ128((rb + nf2*16)*128 + kb));
            }
            #pragma unroll
            for (int mf = 0; mf < 4; ++mf)
                #pragma unroll
                for (int nf = 0; nf < 4; ++nf)
                    mma16816(acc[mf][nf], a_r[mf], &b_r[nf>>1][(nf&1)*2], acc[mf][nf]);
        }
        __syncthreads();
    }

    float g = 0.f;
    if (ep) g = 1.f / (1.f + expf(-gate1[0]));
    const int mrow = m0 + wm*64 + (lane >> 2);
    const int nbase = n0 + wn*32 + (lane & 3)*2;
    #pragma unroll
    for (int mf = 0; mf < 4; ++mf) {
        #pragma unroll
        for (int nf = 0; nf < 4; ++nf) {
            int m = mrow + mf*16;
            int n = nbase + nf*8;
            if (n < Nreal) {
                float2 v0 = make_float2(acc[mf][nf][0], acc[mf][nf][1]);
                float2 v1 = make_float2(acc[mf][nf][2], acc[mf][nf][3]);
                if (ep) {
                    float2 f0 = *(const float2*)(feat + (size_t)m*ldc + n);
                    float2 f1 = *(const float2*)(feat + (size_t)(m+8)*ldc + n);
                    v0.x = g*v0.x + f0.x; v0.y = g*v0.y + f0.y;
                    v1.x = g*v1.x + f1.x; v1.y = g*v1.y + f1.y;
                }
                *(float2*)(C + (size_t)m*ldc + n)     = v0;
                *(float2*)(C + (size_t)(m+8)*ldc + n) = v1;
            }
        }
    }
}

// ---------------- depthwise causal conv (width 4) + bias + SiLU, 4 rows/thread ----------------
__global__ void conv_silu_kernel(const float* __restrict__ cw, const float* __restrict__ cb)
{
    int ch = blockIdx.x * 256 + threadIdx.x;        // 0..DXBC-1 (DXBC = 7*256)
    int r0 = blockIdx.y * 4;
    int l0 = r0 % SEQL;
    float w0 = cw[ch*4+0], w1 = cw[ch*4+1], w2 = cw[ch*4+2], w3 = cw[ch*4+3];
    float bias = cb[ch];
    float v[7];
    #pragma unroll
    for (int t = 0; t < 7; ++t) {
        int lr = l0 + t - 3;
        v[t] = (lr >= 0) ? g_zx[(size_t)(r0 + t - 3) * DPROJ + DIN + ch] : 0.f;
    }
    #pragma unroll
    for (int j = 0; j < 4; ++j) {
        float acc = bias + w0*v[j] + w1*v[j+1] + w2*v[j+2] + w3*v[j+3];
        g_xbc[(size_t)(r0 + j) * DXBC + ch] = acc / (1.f + __expf(-acc));
    }
}

// ---------------- dt (softplus) + per-chunk inclusive cumsum of dt*A, fused ----------------
__global__ void acum_kernel(const float* __restrict__ A_log, const float* __restrict__ dt_bias)
{
    int h  = blockIdx.x % NH;
    int bc = blockIdx.x / NH;
    int l  = threadIdx.x;
    __shared__ float s[CHUNKQ];
    float Ah = -expf(A_log[h]);
    int row = bc * CHUNKQ + l;
    float v = g_zx[(size_t)row * DPROJ + (DIN + DXBC) + h] + dt_bias[h];
    float dt = (v > 20.f) ? v : log1pf(expf(v));
    g_dt[row * NH + h] = dt;
    s[l] = dt * Ah;
    __syncthreads();
    for (int off = 1; off < CHUNKQ; off <<= 1) {
        float t = (l >= off) ? s[l - off] : 0.f;
        __syncthreads();
        s[l] += t;
        __syncthreads();
    }
    g_acum[row * NH + h] = s[l];
    if (l == CHUNKQ - 1) g_alast[bc * NH + h] = s[l];
}

// ---------------- CB[l,s] = sum_n C[l,n]*B[s,n] per chunk (fp32, feeds W) ----------------
#define CB_SMEM_BYTES ((CHUNKQ*CHUNKQ + CHUNKQ*132) * 4)
__global__ void cb_kernel()
{
    float* sm  = (float*)smbuf;
    float* Cs  = sm;
    float* BsT = sm + CHUNKQ*CHUNKQ;
    int bc  = blockIdx.x;
    int tid = threadIdx.x;
    int row0 = bc * CHUNKQ;
    for (int i = tid; i < CHUNKQ*CHUNKQ; i += 256) {
        int l = i >> 7, n = i & 127;
        const float* base = &g_xbc[(size_t)(row0 + l) * DXBC];
        Cs[i]            = base[DIN + DSTATE + n];
        BsT[n*132 + l]   = base[DIN + n];
    }
    __syncthreads();
    int l  = tid >> 1;
    int s0 = (tid & 1) * 64;
    float acc[64] = {};
    for (int n = 0; n < 128; n++) {
        float cv = Cs[l*128 + n];
        const float4* bp = (const float4*)&BsT[n*132 + s0];
        #pragma unroll
        for (int j4 = 0; j4 < 16; j4++) {
            float4 b = bp[j4];
            acc[4*j4+0] += cv*b.x; acc[4*j4+1] += cv*b.y;
            acc[4*j4+2] += cv*b.z; acc[4*j4+3] += cv*b.w;
        }
    }
    float* outp = &g_cb[(size_t)bc*CHUNKQ*CHUNKQ + l*CHUNKQ + s0];
    #pragma unroll
    for (int j4 = 0; j4 < 16; j4++)
        ((float4*)outp)[j4] = make_float4(acc[4*j4], acc[4*j4+1], acc[4*j4+2], acc[4*j4+3]);
}

// ================= states via mma.sync (split bf16) =================
#define STM_SMEM_BYTES 98304
__global__ __launch_bounds__(128, 2) void states_mma()
{
    char* sm = smbuf;
    __shared__ float wfac[128];
    const int h  = blockIdx.x % NH;
    const int bc = blockIdx.x / NH;
    const int tid = threadIdx.x;
    const int row0 = bc * CHUNKQ;

    if (tid < 128) {
        float alast = g_alast[bc*NH + h];
        wfac[tid] = g_dt[(row0+tid)*NH + h] * __expf(alast - g_acum[(row0+tid)*NH + h]);
    }
    __syncthreads();
    for (int i = tid; i < 8192; i += 128) {
        int l = i >> 6, p = i & 63;
        float v = g_xbc[(size_t)(row0+l)*DXBC + h*HD + p] * wfac[l];
        split_store(sm, sm + 16384, SWZ256(p*256 + l*2), v);
    }
    for (int i = tid; i < 16384; i += 128) {
        int l = i >> 7, n = i & 127;
        float v = g_xbc[(size_t)(row0+l)*DXBC + DIN + n];
        split_store(sm + 32768, sm + 65536, SWZ256(n*256 + l*2), v);
    }
    __syncthreads();

    const int lane = tid & 31;
    const int w = tid >> 5;
    const uint32_t base = smem_u32(sm);
    float acc[4][4][4] = {};
    const uint32_t AO[3] = {0u, 0u, 16384u};
    const uint32_t BO[3] = {32768u, 65536u, 32768u};
    #pragma unroll
    for (int pp = 0; pp < 3; ++pp) {
        const uint32_t ab = base + AO[pp], bb = base + BO[pp];
        #pragma unroll
        for (int ks = 0; ks < 8; ++ks) {
            uint32_t a_r[4][4], b_r[2][4];
            const int ra = ((lane>>3)&1)*8 + (lane&7);
            const int ca = ks*32 + ((lane>>4)&1)*16;
            #pragma unroll
            for (int mf = 0; mf < 4; ++mf)
                ldsm4(a_r[mf], ab + SWZ256((ra + mf*16)*256 + ca));
            const int rb = w*32 + ((lane>>4)&1)*8 + (lane&7);
            const int cb2 = ks*32 + ((lane>>3)&1)*16;
            #pragma unroll
            for (int nf2 = 0; nf2 < 2; ++nf2)
                ldsm4(b_r[nf2], bb + SWZ256((rb + nf2*16)*256 + cb2));
            #pragma unroll
            for (int mf = 0; mf < 4; ++mf)
                #pragma unroll
                for (int nf = 0; nf < 4; ++nf)
                    mma16816(acc[mf][nf], a_r[mf], &b_r[nf>>1][(nf&1)*2], acc[mf][nf]);
        }
    }
    float* outb = &g_states[((size_t)(bc*NH) + h) * HD * DSTATE];
    const int mr = lane >> 2;
    const int nb = w*32 + (lane & 3)*2;
    #pragma unroll
    for (int mf = 0; mf < 4; ++mf) {
        #pragma unroll
        for (int nf = 0; nf < 4; ++nf) {
            int p = mf*16 + mr, n = nb + nf*8;
            *(float2*)&outb[p*DSTATE + n]       = make_float2(acc[mf][nf][0], acc[mf][nf][1]);
            *(float2*)&outb[(p+8)*DSTATE + n]   = make_float2(acc[mf][nf][2], acc[mf][nf][3]);
        }
    }
}

// ---------------- inter-chunk state recurrence (one lane per thread) ----------------
__global__ void scan_kernel()
{
    int gl = blockIdx.x * blockDim.x + threadIdx.x;
    int bh = gl >> 13;
    int b = bh / NH, h = bh % NH;
    int e = gl & 8191;
    float S = 0.f;
    for (int c = 0; c < NCH; c++) {
        int bc = b*NCH + c;
        size_t base = ((size_t)(bc*NH) + h) * HD * DSTATE;
        float ed = __expf(g_alast[bc*NH + h]);
        float st = g_states[base + e];
        g_prev[base + e] = S;
        S = S*ed + st;
    }
}

// ================= Y via mma.sync (split bf16) =================
#define YM_SMEM_BYTES 98304
__device__ __forceinline__ void y_mma_block(float acc[2][4][4], uint32_t base,
                                            int lane, int wm, int wn)
{
    const uint32_t AO[3] = {0u, 0u, 32768u};
    const uint32_t BO[3] = {65536u, 81920u, 65536u};
    #pragma unroll
    for (int pp = 0; pp < 3; ++pp) {
        const uint32_t ab = base + AO[pp], bb = base + BO[pp];
        #pragma unroll
        for (int ks = 0; ks < 8; ++ks) {
            uint32_t a_r[2][4], b_r[2][4];
            const int ra = wm*32 + ((lane>>3)&1)*8 + (lane&7);
            const int ca = ks*32 + ((lane>>4)&1)*16;
            #pragma unroll
            for (int mf = 0; mf < 2; ++mf)
                ldsm4(a_r[mf], ab + SWZ256((ra + mf*16)*256 + ca));
            const int rb = wn*32 + ((lane>>4)&1)*8 + (lane&7);
            const int cb2 = ks*32 + ((lane>>3)&1)*16;
            #pragma unroll
            for (int nf2 = 0; nf2 < 2; ++nf2)
                ldsm4(b_r[nf2], bb + SWZ256((rb + nf2*16)*256 + cb2));
            #pragma unroll
            for (int mf = 0; mf < 2; ++mf)
                #pragma unroll
                for (int nf = 0; nf < 4; ++nf)
                    mma16816(acc[mf][nf], a_r[mf], &b_r[nf>>1][(nf&1)*2], acc[mf][nf]);
        }
    }
}

__global__ __launch_bounds__(256, 2) void y_mma(const float* __restrict__ Dv)
{
    char* sm = smbuf;
    __shared__ float acum_s[128], dt_s[128], eAl_s[128];
    const int h  = blockIdx.x % NH;
    const int bc = blockIdx.x / NH;
    const int tid = threadIdx.x;
    const int row0 = bc * CHUNKQ;

    if (tid < 128) {
        float a = g_acum[(row0+tid)*NH + h];
        acum_s[tid] = a;
        eAl_s[tid]  = __expf(a);
        dt_s[tid]   = g_dt[(row0+tid)*NH + h];
    }
    __syncthreads();

    for (int i = tid; i < 16384; i += 256) {
        int l = i >> 7, n = i & 127;
        float v = g_xbc[(size_t)(row0+l)*DXBC + DIN + DSTATE + n] * eAl_s[l];
        split_store(sm, sm + 32768, SWZ256(l*256 + n*2), v);
    }
    const size_t pbase = ((size_t)(bc*NH) + h) * HD * DSTATE;
    for (int i = tid; i < 8192; i += 256) {
        int p = i >> 7, n = i & 127;
        float v = g_prev[pbase + i];
        split_store(sm + 65536, sm + 81920, SWZ256(p*256 + n*2), v);
    }
    __syncthreads();

    const int lane = tid & 31;
    const int wid = tid >> 5;
    const int wm = wid >> 1;
    const int wn = wid & 1;
    const uint32_t base = smem_u32(sm);
    float acc[2][4][4] = {};
    y_mma_block(acc, base, lane, wm, wn);
    __syncthreads();

    for (int i = tid; i < 16384; i += 256) {
        int l = i >> 7, s = i & 127;
        float v = 0.f;
        if (s <= l)
            v = g_cb[(size_t)bc*CHUNKQ*CHUNKQ + i] * __expf(acum_s[l] - acum_s[s]) * dt_s[s];
        split_store(sm, sm + 32768, SWZ256(l*256 + s*2), v);
    }
    for (int i = tid; i < 8192; i += 256) {
        int l = i >> 6, p = i & 63;
        float v = g_xbc[(size_t)(row0+l)*DXBC + h*HD + p];
        split_store(sm + 65536, sm + 81920, SWZ256(p*256 + l*2), v);
    }
    __syncthreads();
    y_mma_block(acc, base, lane, wm, wn);

    const float dval = Dv[h];
    const int mr = lane >> 2;
    const int nb = (lane & 3)*2;
    #pragma unroll
    for (int mf = 0; mf < 2; ++mf) {
        #pragma unroll
        for (int nf = 0; nf < 4; ++nf) {
            int p = wn*32 + nf*8 + nb;
            #pragma unroll
            for (int rr = 0; rr < 2; ++rr) {
                int l = wm*32 + mf*16 + mr + rr*8;
                uint32_t o0 = SWZ256(p*256 + l*2);
                uint32_t o1 = SWZ256((p+1)*256 + l*2);
                float x0 = __bfloat162float(*(__nv_bfloat16*)(sm + 65536 + o0))
                         + __bfloat162float(*(__nv_bfloat16*)(sm + 81920 + o0));
                float x1 = __bfloat162float(*(__nv_bfloat16*)(sm + 65536 + o1))
                         + __bfloat162float(*(__nv_bfloat16*)(sm + 81920 + o1));
                float2 v = make_float2(acc[mf][nf][rr*2+0] + dval*x0,
                                       acc[mf][nf][rr*2+1] + dval*x1);
                *(float2*)&g_y[(size_t)(row0+l)*DIN + h*HD + p] = v;
            }
        }
    }
}

// ---------------- gating + RMSNorm + fused split_a for GEMM2 ----------------
// writes normalized y directly into g_a2 in the 3K-duplicated split layout.
__global__ void norm_split_kernel(const float* __restrict__ norm_w,
                                  __nv_bfloat16* __restrict__ O)
{
    __shared__ float tbuf[DIN];
    __shared__ float red[256];
    int row = blockIdx.x;
    int tid = threadIdx.x;
    float partial = 0.f;
    for (int i = tid; i < DIN; i += 256) {
        float yv = g_y[(size_t)row*DIN + i];
        float zv = g_zx[(size_t)row*DPROJ + i];
        float t  = yv * (zv / (1.f + __expf(-zv)));
        tbuf[i] = t;
        partial += t*t;
    }
    red[tid] = partial;
    __syncthreads();
    for (int s = 128; s > 0; s >>= 1) {
        if (tid < s) red[tid] += red[tid + s];
        __syncthreads();
    }
    float scale = rsqrtf(red[0] / (float)DIN + 1e-5f);
    __nv_bfloat16* ob = O + (size_t)row * KP2;
    for (int i = tid; i < DIN; i += 256) {
        float v = tbuf[i] * scale * norm_w[i];
        __nv_bfloat16 hi = __float2bfloat16(v);
        __nv_bfloat16 lo = __float2bfloat16(v - __bfloat162float(hi));
        ob[i] = hi; ob[DIN + i] = hi; ob[2*DIN + i] = lo;
    }
}

// ---------------- launch ----------------
extern "C" void kernel_launch(void* const* d_in, const int* in_sizes, int n_in,
                              void* d_out, int out_size)
{
    const float* feature = (const float*)d_in[0];
    const float* gate1   = (const float*)d_in[1];
    const float* in_w    = (const float*)d_in[2];
    const float* conv_w  = (const float*)d_in[3];
    const float* conv_b  = (const float*)d_in[4];
    const float* dt_bias = (const float*)d_in[5];
    const float* A_log   = (const float*)d_in[6];
    const float* Dv      = (const float*)d_in[7];
    const float* norm_w  = (const float*)d_in[8];
    const float* out_w   = (const float*)d_in[9];
    float* out = (float*)d_out;

    void* p_zx; cudaGetSymbolAddress(&p_zx, g_zx);
    void* p_a2; cudaGetSymbolAddress(&p_a2, g_a2);
    void* p_b2; cudaGetSymbolAddress(&p_b2, g_b2);
    __nv_bfloat16* a2 = (__nv_bfloat16*)p_a2;
    __nv_bfloat16* b2 = (__nv_bfloat16*)p_b2;

    cudaFuncSetAttribute(cb_kernel,  cudaFuncAttributeMaxDynamicSharedMemorySize, CB_SMEM_BYTES);
    cudaFuncSetAttribute(states_mma, cudaFuncAttributeMaxDynamicSharedMemorySize, STM_SMEM_BYTES);
    cudaFuncSetAttribute(y_mma,      cudaFuncAttributeMaxDynamicSharedMemorySize, YM_SMEM_BYTES);
    cudaFuncSetAttribute(gemm_mma,   cudaFuncAttributeMaxDynamicSharedMemorySize, GEMM_SMEM_BYTES);

    // 1. split conversion + GEMM1 (tensor cores)
    split_a_kernel<<<(NROWS*DMODEL + 255)/256, 256>>>(feature, a2, NROWS, DMODEL);
    split_b_kernel<<<(NPAD1*DMODEL + 255)/256, 256>>>(in_w, b2, DPROJ, NPAD1, DMODEL);
    gemm_mma<<<dim3(NPAD1/128, NROWS/128), 256, GEMM_SMEM_BYTES>>>(
        a2, b2, (float*)p_zx, KP1, DPROJ, DPROJ, nullptr, nullptr, 0);
    // 2. conv + silu (4 rows per thread)
    conv_silu_kernel<<<dim3(DXBC/256, NROWS/4), 256>>>(conv_w, conv_b);
    // 3. dt + per-chunk cumsum (fused)
    acum_kernel<<<NBC*NH, CHUNKQ>>>(A_log, dt_bias);
    // 4. CB per chunk (fp32)
    cb_kernel<<<NBC, 256, CB_SMEM_BYTES>>>();
    // 5. chunk states (tensor cores, split bf16)
    states_mma<<<NBC*NH, 128, STM_SMEM_BYTES>>>();
    // 6. inter-chunk recurrence
    scan_kernel<<<(BSZ*NH*HD*DSTATE)/512, 512>>>();
    // 7. Y (tensor cores, split bf16)
    y_mma<<<NBC*NH, 256, YM_SMEM_BYTES>>>(Dv);
    // 8. gating + RMSNorm + split for GEMM2 (fused)
    norm_split_kernel<<<NROWS, 256>>>(norm_w, a2);
    // 9. split B + GEMM2 (tensor cores) + residual epilogue
    split_b_kernel<<<(DMODEL*DIN + 255)/256, 256>>>(out_w, b2, DMODEL, DMODEL, DIN);
    gemm_mma<<<dim3(DMODEL/128, NROWS/128), 256, GEMM_SMEM_BYTES>>>(
        a2, b2, out, KP2, DMODEL, DMODEL, feature, gate1, 1);
}